// round 15
// baseline (speedup 1.0000x reference)
#include <cuda_runtime.h>

#define Hd 128
#define Wd 128
#define HWd (128*128)
typedef unsigned long long ull;

// Scratch (device globals: allocation-free rule)
__device__ float g_t2[4 * 64 * HWd];   // conv1 output (active blocks only)
__device__ float g_t3[4 * 64 * HWd];   // conv2 output, relu'd (active blocks only)
__device__ int   g_nact;
__device__ int   g_act[256];

// ---- f32x2 packed helpers --------------------------------------------------
static __device__ __forceinline__ ull pk2(float a, float b) {
    ull r;
    asm("mov.b64 %0, {%1, %2};" : "=l"(r) : "r"(__float_as_uint(a)), "r"(__float_as_uint(b)));
    return r;
}
static __device__ __forceinline__ void upk2(ull v, float& a, float& b) {
    unsigned ua, ub;
    asm("mov.b64 {%0, %1}, %2;" : "=r"(ua), "=r"(ub) : "l"(v));
    a = __uint_as_float(ua); b = __uint_as_float(ub);
}
static __device__ __forceinline__ void fma2(ull& d, ull a, ull b) {
    asm("fma.rn.f32x2 %0, %1, %2, %0;" : "+l"(d) : "l"(a), "l"(b));
}

// ---------------------------------------------------------------------------
// K1: conv1 (1x1 grouped, 256->64 per group) + relu for ACTIVE blocks,
// checked directly against mask (no compaction dependency).
// grid 513: bid < 512 -> (gb = bid>>1, ph = bid&1) conv1 role;
//           bid == 512 -> mask-compaction role (fills g_act/g_nact for k2/k3).
// ---------------------------------------------------------------------------
extern "C" __global__ void __launch_bounds__(256, 2)
k1_conv1(const float* __restrict__ x, const float* __restrict__ mask,
         const float* __restrict__ w1)
{
    int tid = threadIdx.x;

    if (blockIdx.x == 512) {
        // ---- compaction role (for k2/k3) ----
        __shared__ int cnt;
        if (tid == 0) cnt = 0;
        __syncthreads();
        if (mask[tid] > 0.5f) { int p = atomicAdd(&cnt, 1); g_act[p] = tid; }
        __syncthreads();
        if (tid == 0) g_nact = cnt;
        return;
    }

    int gb = blockIdx.x >> 1, ph = blockIdx.x & 1;
    if (mask[gb] <= 0.5f) return;
    int g = gb >> 6, blk = gb & 63;
    int bi = blk >> 3, bj = blk & 7;

    extern __shared__ float sm[];
    float* ws = sm;             // [256 ic][68] (64 oc + pad)
    float* xs = sm + 256 * 68;  // [16 ic][128 px]

    for (int e = tid; e < 64 * 256; e += 256) {
        int oc = e >> 8, ic = e & 255;
        ws[ic * 68 + oc] = w1[(size_t)(g * 64 + oc) * 256 + ic];
    }

    int ocg = tid >> 6, pt = tid & 63;
    int oc0 = ocg * 16;
    int pxl = tid & 127;
    int r0  = (tid >> 7) * 8;
    int py_l = ph * 8 + (pxl >> 4), px_c = pxl & 15;
    const float* xb = x + (size_t)(g * 256) * HWd + (bi * 16 + py_l) * Wd + bj * 16 + px_c;

    ull acc[8][2];
#pragma unroll
    for (int p = 0; p < 8; ++p) { acc[p][0] = 0ull; acc[p][1] = 0ull; }

    for (int c = 0; c < 16; ++c) {
#pragma unroll
        for (int rr = 0; rr < 8; ++rr)
            xs[(r0 + rr) * 128 + pxl] = xb[(size_t)(c * 16 + r0 + rr) * HWd];
        __syncthreads();
#pragma unroll 2
        for (int r = 0; r < 16; ++r) {
            const float* xr = xs + r * 128 + pt;
            float v0 = xr[0], v1 = xr[64];
            ull t0 = pk2(v0, v0), t1 = pk2(v1, v1);
            const ulonglong2* wp = (const ulonglong2*)(ws + (c * 16 + r) * 68 + oc0);
            ulonglong2 wa = wp[0], wb = wp[1], wc = wp[2], wd = wp[3];
            fma2(acc[0][0], wa.x, t0); fma2(acc[0][1], wa.x, t1);
            fma2(acc[1][0], wa.y, t0); fma2(acc[1][1], wa.y, t1);
            fma2(acc[2][0], wb.x, t0); fma2(acc[2][1], wb.x, t1);
            fma2(acc[3][0], wb.y, t0); fma2(acc[3][1], wb.y, t1);
            fma2(acc[4][0], wc.x, t0); fma2(acc[4][1], wc.x, t1);
            fma2(acc[5][0], wc.y, t0); fma2(acc[5][1], wc.y, t1);
            fma2(acc[6][0], wd.x, t0); fma2(acc[6][1], wd.x, t1);
            fma2(acc[7][0], wd.y, t0); fma2(acc[7][1], wd.y, t1);
        }
        __syncthreads();
    }

    float* t2p = g_t2 + (size_t)(g * 64 + oc0) * HWd + (bi * 16 + ph * 8) * Wd + bj * 16;
#pragma unroll
    for (int p = 0; p < 8; ++p)
#pragma unroll
        for (int k = 0; k < 2; ++k) {
            float a, b; upk2(acc[p][k], a, b);
            int px = pt + 64 * k;
            size_t o = (size_t)(2 * p) * HWd + (px >> 4) * Wd + (px & 15);
            t2p[o]       = fmaxf(a, 0.f);
            t2p[o + HWd] = fmaxf(b, 0.f);
        }
}

// ---------------------------------------------------------------------------
// K2: conv2 (3x3 grouped) + relu for active blocks, PLUS inactive-block
// relu-copy folded into the same grid (bid >= 512 -> copy role).
// ---------------------------------------------------------------------------
extern "C" __global__ void __launch_bounds__(512, 2)
k2_conv2(const float* __restrict__ x, const float* __restrict__ mask,
         const float* __restrict__ w2, float* __restrict__ out)
{
    int tid = threadIdx.x;

    if (blockIdx.x >= 512) {
        // ---- inactive relu-copy role ----
        int cb = blockIdx.x - 512;
        int gb = cb >> 1;
        if (mask[gb] > 0.5f) return;
        int half = cb & 1;
        int g = gb >> 6, blk = gb & 63;
        int bi = blk >> 3, bj = blk & 7;
        int ch0 = tid >> 6;              // 0..7
        int s = tid & 63;
        int py = s >> 2, c4 = s & 3;
        size_t base = (size_t)(g * 256 + half * 128 + ch0) * HWd
                    + (bi * 16 + py) * Wd + bj * 16;
        const float4* xp = (const float4*)(x + base) + c4;
        float4*       op = (float4*)(out + base) + c4;
#pragma unroll
        for (int m = 0; m < 16; ++m) {   // channels ch0+8m
            float4 v = xp[(size_t)(8 * m) * (HWd / 4)];
            v.x = fmaxf(v.x, 0.f); v.y = fmaxf(v.y, 0.f);
            v.z = fmaxf(v.z, 0.f); v.w = fmaxf(v.w, 0.f);
            op[(size_t)(8 * m) * (HWd / 4)] = v;
        }
        return;
    }

    // ---- conv2 compute role ----
    int aidx = blockIdx.x >> 1, sub = blockIdx.x & 1;
    if (aidx >= g_nact) return;
    int act = g_act[aidx];
    int g = act >> 6, blk = act & 63, bi = blk >> 3, bj = blk & 7;

    extern __shared__ float sm[];
    float* t2s = sm;             // [64 ch][324]
    float* w2s = sm + 64 * 324;  // [144][36]
    __shared__ float nbact[9];

    const float* mg = mask + g * 64;
    if (tid < 9) {
        int dy = tid / 3, dx = tid % 3;
        int by = bi - 1 + dy, bx = bj - 1 + dx;
        nbact[tid] = ((unsigned)by < 8u && (unsigned)bx < 8u && mg[by * 8 + bx] > 0.5f) ? 1.f : 0.f;
    }
    __syncthreads();

    const float* t2g = g_t2 + (size_t)(g * 64) * HWd;
    int row0 = bi * 16 - 1, col0 = bj * 16 - 1;
    for (int e = tid; e < 64 * 324; e += 512) {
        int ch = e / 324, hp = e - ch * 324;
        int hy = hp / 18, hx = hp - hy * 18;
        int ndy = (hy + 15) >> 4;
        int ndx = (hx + 15) >> 4;
        float v = 0.f;
        if (nbact[ndy * 3 + ndx] > 0.f)
            v = t2g[(size_t)ch * HWd + (row0 + hy) * Wd + col0 + hx];
        t2s[ch * 324 + hp] = v;
    }

    int w = tid >> 5, lane = tid & 31;
    int ocg = w >> 2, rg = w & 3;
    int oc0 = ocg * 8;
    int cx = lane & 15;
    int ry0 = rg * 4 + (lane >> 4) * 2;      // output rows ry0, ry0+1

    ull acc[4][2];
#pragma unroll
    for (int p = 0; p < 4; ++p) { acc[p][0] = 0ull; acc[p][1] = 0ull; }

    const size_t wbase = (size_t)(g * 64 + sub * 32) * 576;

    for (int chk = 0; chk < 4; ++chk) {
        __syncthreads();                 // also orders halo fill before 1st chunk
        for (int e = tid; e < 32 * 144; e += 512) {
            int oc = e / 144, rt = e - oc * 144;
            w2s[rt * 36 + oc] = w2[wbase + (size_t)oc * 576 + chk * 144 + rt];
        }
        __syncthreads();

        for (int icl = 0; icl < 16; ++icl) {
            const float* trow = t2s + (chk * 16 + icl) * 324;
            ull pt[4][3];
#pragma unroll
            for (int r = 0; r < 4; ++r) {
                const float* rr = trow + (ry0 + r) * 18 + cx;
                float v0 = rr[0], v1 = rr[1], v2 = rr[2];
                pt[r][0] = pk2(v0, v0); pt[r][1] = pk2(v1, v1); pt[r][2] = pk2(v2, v2);
            }
            const float* wrow = w2s + icl * 9 * 36 + oc0;
#pragma unroll
            for (int dy = 0; dy < 3; ++dy) {
#pragma unroll
                for (int dx = 0; dx < 3; ++dx) {
                    const ulonglong2* wp = (const ulonglong2*)(wrow + (dy * 3 + dx) * 36);
                    ulonglong2 wa = wp[0], wb = wp[1];
                    ull tv0 = pt[dy][dx], tv1 = pt[dy + 1][dx];
                    fma2(acc[0][0], wa.x, tv0); fma2(acc[0][1], wa.x, tv1);
                    fma2(acc[1][0], wa.y, tv0); fma2(acc[1][1], wa.y, tv1);
                    fma2(acc[2][0], wb.x, tv0); fma2(acc[2][1], wb.x, tv1);
                    fma2(acc[3][0], wb.y, tv0); fma2(acc[3][1], wb.y, tv1);
                }
            }
        }
    }

    float* t3p = g_t3 + (size_t)(g * 64 + sub * 32 + oc0) * HWd + (bi * 16) * Wd + bj * 16;
#pragma unroll
    for (int p = 0; p < 4; ++p)
#pragma unroll
        for (int k = 0; k < 2; ++k) {
            float a, b; upk2(acc[p][k], a, b);
            size_t o = (size_t)(2 * p) * HWd + (ry0 + k) * Wd + cx;
            t3p[o]       = fmaxf(a, 0.f);
            t3p[o + HWd] = fmaxf(b, 0.f);
        }
}

// ---------------------------------------------------------------------------
// K3: conv3 (1x1 grouped, 64->256) + residual + relu, ACTIVE blocks only.
// grid 1024: (aidx, sub of 128 oc, ph pixel-half). 256 threads. (R13 config —
// measured best at 52.2us; R14's 4-way px split regressed to 54.2us.)
// ---------------------------------------------------------------------------
extern "C" __global__ void __launch_bounds__(256)
k3_active(const float* __restrict__ x, const float* __restrict__ w3,
          float* __restrict__ out)
{
    int aidx = blockIdx.x >> 2, sub = (blockIdx.x >> 1) & 1, ph = blockIdx.x & 1;
    if (aidx >= g_nact) return;
    int act = g_act[aidx];
    int g = act >> 6, blk = act & 63;
    int bi = blk >> 3, bj = blk & 7;
    int tid = threadIdx.x;

    extern __shared__ float sm[];
    float* t3s = sm;             // [64 ic][128 px]
    float* w3s = sm + 64 * 128;  // [64 ic][132]

    const float* t3g = g_t3 + (size_t)(g * 64) * HWd + (bi * 16 + ph * 8) * Wd + bj * 16;
    for (int e = tid; e < 64 * 128; e += 256) {
        int ic = e >> 7, px = e & 127;
        t3s[e] = t3g[(size_t)ic * HWd + (px >> 4) * Wd + (px & 15)];
    }
    for (int e = tid; e < 64 * 128; e += 256) {
        int oc = e >> 6, ic = e & 63;
        w3s[ic * 132 + oc] = w3[(size_t)(g * 256 + sub * 128 + oc) * 64 + ic];
    }
    __syncthreads();

    int og = tid >> 5, lane = tid & 31;

    for (int pass = 0; pass < 2; ++pass) {
        int ocb = pass * 64 + og * 8;
        ull acc[4][4];
#pragma unroll
        for (int p = 0; p < 4; ++p)
#pragma unroll
            for (int k = 0; k < 4; ++k) acc[p][k] = 0ull;

        for (int ic = 0; ic < 64; ++ic) {
            const ulonglong2* wp = (const ulonglong2*)(w3s + ic * 132 + ocb);
            ulonglong2 wa = wp[0], wb = wp[1];
            const float* tr = t3s + ic * 128 + lane;
            float v0 = tr[0], v1 = tr[32], v2 = tr[64], v3 = tr[96];
            ull t0 = pk2(v0, v0), t1 = pk2(v1, v1), t2 = pk2(v2, v2), t3 = pk2(v3, v3);
            fma2(acc[0][0], wa.x, t0); fma2(acc[0][1], wa.x, t1);
            fma2(acc[0][2], wa.x, t2); fma2(acc[0][3], wa.x, t3);
            fma2(acc[1][0], wa.y, t0); fma2(acc[1][1], wa.y, t1);
            fma2(acc[1][2], wa.y, t2); fma2(acc[1][3], wa.y, t3);
            fma2(acc[2][0], wb.x, t0); fma2(acc[2][1], wb.x, t1);
            fma2(acc[2][2], wb.x, t2); fma2(acc[2][3], wb.x, t3);
            fma2(acc[3][0], wb.y, t0); fma2(acc[3][1], wb.y, t1);
            fma2(acc[3][2], wb.y, t2); fma2(acc[3][3], wb.y, t3);
        }

        size_t base = (size_t)(g * 256 + sub * 128 + ocb) * HWd
                    + (bi * 16 + ph * 8) * Wd + bj * 16;
        const float* xp = x + base;
        float*       op = out + base;
#pragma unroll
        for (int p = 0; p < 4; ++p)
#pragma unroll
            for (int k = 0; k < 4; ++k) {
                int px = lane + 32 * k;
                float a, b; upk2(acc[p][k], a, b);
                size_t o = (size_t)(2 * p) * HWd + (px >> 4) * Wd + (px & 15);
                op[o]       = fmaxf(xp[o] + a, 0.f);
                op[o + HWd] = fmaxf(xp[o + HWd] + b, 0.f);
            }
    }
}

// ---------------------------------------------------------------------------
extern "C" void kernel_launch(void* const* d_in, const int* in_sizes, int n_in,
                              void* d_out, int out_size)
{
    (void)in_sizes; (void)n_in; (void)out_size;
    const float* x    = (const float*)d_in[0];
    const float* mask = (const float*)d_in[1];
    const float* w1   = (const float*)d_in[2];
    const float* w2   = (const float*)d_in[3];
    const float* w3   = (const float*)d_in[4];
    float* out = (float*)d_out;

    const int smem1 = (256 * 68 + 16 * 128) * 4;       // 77824
    const int smem2 = (64 * 324 + 144 * 36) * 4;       // 103680
    const int smem3 = (64 * 128 + 64 * 132) * 4;       // 66560
    cudaFuncSetAttribute(k1_conv1, cudaFuncAttributeMaxDynamicSharedMemorySize, smem1);
    cudaFuncSetAttribute(k2_conv2, cudaFuncAttributeMaxDynamicSharedMemorySize, smem2);
    cudaFuncSetAttribute(k3_active, cudaFuncAttributeMaxDynamicSharedMemorySize, smem3);

    k1_conv1<<<513, 256, smem1>>>(x, mask, w1);
    k2_conv2<<<1024, 512, smem2>>>(x, mask, w2, out);
    k3_active<<<1024, 256, smem3>>>(x, w3, out);
}

// round 16
// speedup vs baseline: 1.0277x; 1.0277x over previous
#include <cuda_runtime.h>

#define Hd 128
#define Wd 128
#define HWd (128*128)
typedef unsigned long long ull;

// Scratch (device globals: allocation-free rule)
__device__ float g_t2[4 * 64 * HWd];   // conv1 output (active blocks only)
__device__ float g_t3[4 * 64 * HWd];   // conv2 output, relu'd (active blocks only)
__device__ int   g_nact;
__device__ int   g_act[256];

// ---- f32x2 packed helpers --------------------------------------------------
static __device__ __forceinline__ ull pk2(float a, float b) {
    ull r;
    asm("mov.b64 %0, {%1, %2};" : "=l"(r) : "r"(__float_as_uint(a)), "r"(__float_as_uint(b)));
    return r;
}
static __device__ __forceinline__ void upk2(ull v, float& a, float& b) {
    unsigned ua, ub;
    asm("mov.b64 {%0, %1}, %2;" : "=r"(ua), "=r"(ub) : "l"(v));
    a = __uint_as_float(ua); b = __uint_as_float(ub);
}
static __device__ __forceinline__ void fma2(ull& d, ull a, ull b) {
    asm("fma.rn.f32x2 %0, %1, %2, %0;" : "+l"(d) : "l"(a), "l"(b));
}

// ---------------------------------------------------------------------------
// K1: conv1 (1x1 grouped, 256->64 per group) + relu for ACTIVE blocks.
// grid 513: bid < 512 -> (gb, ph) conv1 role; bid == 512 -> mask compaction.
// *** Register double-buffered x staging: chunk c+1's 8 LDGs issue before
// chunk c's compute, hiding DRAM latency behind ~400 cycles of FFMA2. ***
// ---------------------------------------------------------------------------
extern "C" __global__ void __launch_bounds__(256, 2)
k1_conv1(const float* __restrict__ x, const float* __restrict__ mask,
         const float* __restrict__ w1)
{
    int tid = threadIdx.x;

    if (blockIdx.x == 512) {
        // ---- compaction role (for k2/k3) ----
        __shared__ int cnt;
        if (tid == 0) cnt = 0;
        __syncthreads();
        if (mask[tid] > 0.5f) { int p = atomicAdd(&cnt, 1); g_act[p] = tid; }
        __syncthreads();
        if (tid == 0) g_nact = cnt;
        return;
    }

    int gb = blockIdx.x >> 1, ph = blockIdx.x & 1;
    if (mask[gb] <= 0.5f) return;
    int g = gb >> 6, blk = gb & 63;
    int bi = blk >> 3, bj = blk & 7;

    extern __shared__ float sm[];
    float* ws = sm;             // [256 ic][68] (64 oc + pad)
    float* xs = sm + 256 * 68;  // [16 ic][128 px]

    for (int e = tid; e < 64 * 256; e += 256) {
        int oc = e >> 8, ic = e & 255;
        ws[ic * 68 + oc] = w1[(size_t)(g * 64 + oc) * 256 + ic];
    }

    int ocg = tid >> 6, pt = tid & 63;
    int oc0 = ocg * 16;
    int pxl = tid & 127;
    int r0  = (tid >> 7) * 8;
    int py_l = ph * 8 + (pxl >> 4), px_c = pxl & 15;
    const float* xb = x + (size_t)(g * 256) * HWd + (bi * 16 + py_l) * Wd + bj * 16 + px_c;

    ull acc[8][2];
#pragma unroll
    for (int p = 0; p < 8; ++p) { acc[p][0] = 0ull; acc[p][1] = 0ull; }

    float pref[8];
#pragma unroll
    for (int rr = 0; rr < 8; ++rr)
        pref[rr] = xb[(size_t)(r0 + rr) * HWd];

    for (int c = 0; c < 16; ++c) {
        // commit prefetched chunk c to smem
#pragma unroll
        for (int rr = 0; rr < 8; ++rr)
            xs[(r0 + rr) * 128 + pxl] = pref[rr];
        __syncthreads();
        // issue chunk c+1's global loads (latency hides behind compute below)
        if (c + 1 < 16) {
#pragma unroll
            for (int rr = 0; rr < 8; ++rr)
                pref[rr] = xb[(size_t)((c + 1) * 16 + r0 + rr) * HWd];
        }
#pragma unroll 2
        for (int r = 0; r < 16; ++r) {
            const float* xr = xs + r * 128 + pt;
            float v0 = xr[0], v1 = xr[64];
            ull t0 = pk2(v0, v0), t1 = pk2(v1, v1);
            const ulonglong2* wp = (const ulonglong2*)(ws + (c * 16 + r) * 68 + oc0);
            ulonglong2 wa = wp[0], wb = wp[1], wc = wp[2], wd = wp[3];
            fma2(acc[0][0], wa.x, t0); fma2(acc[0][1], wa.x, t1);
            fma2(acc[1][0], wa.y, t0); fma2(acc[1][1], wa.y, t1);
            fma2(acc[2][0], wb.x, t0); fma2(acc[2][1], wb.x, t1);
            fma2(acc[3][0], wb.y, t0); fma2(acc[3][1], wb.y, t1);
            fma2(acc[4][0], wc.x, t0); fma2(acc[4][1], wc.x, t1);
            fma2(acc[5][0], wc.y, t0); fma2(acc[5][1], wc.y, t1);
            fma2(acc[6][0], wd.x, t0); fma2(acc[6][1], wd.x, t1);
            fma2(acc[7][0], wd.y, t0); fma2(acc[7][1], wd.y, t1);
        }
        __syncthreads();
    }

    float* t2p = g_t2 + (size_t)(g * 64 + oc0) * HWd + (bi * 16 + ph * 8) * Wd + bj * 16;
#pragma unroll
    for (int p = 0; p < 8; ++p)
#pragma unroll
        for (int k = 0; k < 2; ++k) {
            float a, b; upk2(acc[p][k], a, b);
            int px = pt + 64 * k;
            size_t o = (size_t)(2 * p) * HWd + (px >> 4) * Wd + (px & 15);
            t2p[o]       = fmaxf(a, 0.f);
            t2p[o + HWd] = fmaxf(b, 0.f);
        }
}

// ---------------------------------------------------------------------------
// K2: conv2 (3x3 grouped) + relu for active blocks, PLUS inactive-block
// relu-copy folded into the same grid (bid >= 512 -> copy role).
// ---------------------------------------------------------------------------
extern "C" __global__ void __launch_bounds__(512, 2)
k2_conv2(const float* __restrict__ x, const float* __restrict__ mask,
         const float* __restrict__ w2, float* __restrict__ out)
{
    int tid = threadIdx.x;

    if (blockIdx.x >= 512) {
        // ---- inactive relu-copy role ----
        int cb = blockIdx.x - 512;
        int gb = cb >> 1;
        if (mask[gb] > 0.5f) return;
        int half = cb & 1;
        int g = gb >> 6, blk = gb & 63;
        int bi = blk >> 3, bj = blk & 7;
        int ch0 = tid >> 6;              // 0..7
        int s = tid & 63;
        int py = s >> 2, c4 = s & 3;
        size_t base = (size_t)(g * 256 + half * 128 + ch0) * HWd
                    + (bi * 16 + py) * Wd + bj * 16;
        const float4* xp = (const float4*)(x + base) + c4;
        float4*       op = (float4*)(out + base) + c4;
#pragma unroll
        for (int m = 0; m < 16; ++m) {   // channels ch0+8m
            float4 v = xp[(size_t)(8 * m) * (HWd / 4)];
            v.x = fmaxf(v.x, 0.f); v.y = fmaxf(v.y, 0.f);
            v.z = fmaxf(v.z, 0.f); v.w = fmaxf(v.w, 0.f);
            op[(size_t)(8 * m) * (HWd / 4)] = v;
        }
        return;
    }

    // ---- conv2 compute role ----
    int aidx = blockIdx.x >> 1, sub = blockIdx.x & 1;
    if (aidx >= g_nact) return;
    int act = g_act[aidx];
    int g = act >> 6, blk = act & 63, bi = blk >> 3, bj = blk & 7;

    extern __shared__ float sm[];
    float* t2s = sm;             // [64 ch][324]
    float* w2s = sm + 64 * 324;  // [144][36]
    __shared__ float nbact[9];

    const float* mg = mask + g * 64;
    if (tid < 9) {
        int dy = tid / 3, dx = tid % 3;
        int by = bi - 1 + dy, bx = bj - 1 + dx;
        nbact[tid] = ((unsigned)by < 8u && (unsigned)bx < 8u && mg[by * 8 + bx] > 0.5f) ? 1.f : 0.f;
    }
    __syncthreads();

    const float* t2g = g_t2 + (size_t)(g * 64) * HWd;
    int row0 = bi * 16 - 1, col0 = bj * 16 - 1;
    for (int e = tid; e < 64 * 324; e += 512) {
        int ch = e / 324, hp = e - ch * 324;
        int hy = hp / 18, hx = hp - hy * 18;
        int ndy = (hy + 15) >> 4;
        int ndx = (hx + 15) >> 4;
        float v = 0.f;
        if (nbact[ndy * 3 + ndx] > 0.f)
            v = t2g[(size_t)ch * HWd + (row0 + hy) * Wd + col0 + hx];
        t2s[ch * 324 + hp] = v;
    }

    int w = tid >> 5, lane = tid & 31;
    int ocg = w >> 2, rg = w & 3;
    int oc0 = ocg * 8;
    int cx = lane & 15;
    int ry0 = rg * 4 + (lane >> 4) * 2;      // output rows ry0, ry0+1

    ull acc[4][2];
#pragma unroll
    for (int p = 0; p < 4; ++p) { acc[p][0] = 0ull; acc[p][1] = 0ull; }

    const size_t wbase = (size_t)(g * 64 + sub * 32) * 576;

    for (int chk = 0; chk < 4; ++chk) {
        __syncthreads();                 // also orders halo fill before 1st chunk
        for (int e = tid; e < 32 * 144; e += 512) {
            int oc = e / 144, rt = e - oc * 144;
            w2s[rt * 36 + oc] = w2[wbase + (size_t)oc * 576 + chk * 144 + rt];
        }
        __syncthreads();

        for (int icl = 0; icl < 16; ++icl) {
            const float* trow = t2s + (chk * 16 + icl) * 324;
            ull pt[4][3];
#pragma unroll
            for (int r = 0; r < 4; ++r) {
                const float* rr = trow + (ry0 + r) * 18 + cx;
                float v0 = rr[0], v1 = rr[1], v2 = rr[2];
                pt[r][0] = pk2(v0, v0); pt[r][1] = pk2(v1, v1); pt[r][2] = pk2(v2, v2);
            }
            const float* wrow = w2s + icl * 9 * 36 + oc0;
#pragma unroll
            for (int dy = 0; dy < 3; ++dy) {
#pragma unroll
                for (int dx = 0; dx < 3; ++dx) {
                    const ulonglong2* wp = (const ulonglong2*)(wrow + (dy * 3 + dx) * 36);
                    ulonglong2 wa = wp[0], wb = wp[1];
                    ull tv0 = pt[dy][dx], tv1 = pt[dy + 1][dx];
                    fma2(acc[0][0], wa.x, tv0); fma2(acc[0][1], wa.x, tv1);
                    fma2(acc[1][0], wa.y, tv0); fma2(acc[1][1], wa.y, tv1);
                    fma2(acc[2][0], wb.x, tv0); fma2(acc[2][1], wb.x, tv1);
                    fma2(acc[3][0], wb.y, tv0); fma2(acc[3][1], wb.y, tv1);
                }
            }
        }
    }

    float* t3p = g_t3 + (size_t)(g * 64 + sub * 32 + oc0) * HWd + (bi * 16) * Wd + bj * 16;
#pragma unroll
    for (int p = 0; p < 4; ++p)
#pragma unroll
        for (int k = 0; k < 2; ++k) {
            float a, b; upk2(acc[p][k], a, b);
            size_t o = (size_t)(2 * p) * HWd + (ry0 + k) * Wd + cx;
            t3p[o]       = fmaxf(a, 0.f);
            t3p[o + HWd] = fmaxf(b, 0.f);
        }
}

// ---------------------------------------------------------------------------
// K3: conv3 (1x1 grouped, 64->256) + residual + relu, ACTIVE blocks only.
// grid 1024: (aidx, sub of 128 oc, ph pixel-half). 256 threads.
// ---------------------------------------------------------------------------
extern "C" __global__ void __launch_bounds__(256)
k3_active(const float* __restrict__ x, const float* __restrict__ w3,
          float* __restrict__ out)
{
    int aidx = blockIdx.x >> 2, sub = (blockIdx.x >> 1) & 1, ph = blockIdx.x & 1;
    if (aidx >= g_nact) return;
    int act = g_act[aidx];
    int g = act >> 6, blk = act & 63;
    int bi = blk >> 3, bj = blk & 7;
    int tid = threadIdx.x;

    extern __shared__ float sm[];
    float* t3s = sm;             // [64 ic][128 px]
    float* w3s = sm + 64 * 128;  // [64 ic][132]

    const float* t3g = g_t3 + (size_t)(g * 64) * HWd + (bi * 16 + ph * 8) * Wd + bj * 16;
    for (int e = tid; e < 64 * 128; e += 256) {
        int ic = e >> 7, px = e & 127;
        t3s[e] = t3g[(size_t)ic * HWd + (px >> 4) * Wd + (px & 15)];
    }
    for (int e = tid; e < 64 * 128; e += 256) {
        int oc = e >> 6, ic = e & 63;
        w3s[ic * 132 + oc] = w3[(size_t)(g * 256 + sub * 128 + oc) * 64 + ic];
    }
    __syncthreads();

    int og = tid >> 5, lane = tid & 31;

    for (int pass = 0; pass < 2; ++pass) {
        int ocb = pass * 64 + og * 8;
        ull acc[4][4];
#pragma unroll
        for (int p = 0; p < 4; ++p)
#pragma unroll
            for (int k = 0; k < 4; ++k) acc[p][k] = 0ull;

        for (int ic = 0; ic < 64; ++ic) {
            const ulonglong2* wp = (const ulonglong2*)(w3s + ic * 132 + ocb);
            ulonglong2 wa = wp[0], wb = wp[1];
            const float* tr = t3s + ic * 128 + lane;
            float v0 = tr[0], v1 = tr[32], v2 = tr[64], v3 = tr[96];
            ull t0 = pk2(v0, v0), t1 = pk2(v1, v1), t2 = pk2(v2, v2), t3 = pk2(v3, v3);
            fma2(acc[0][0], wa.x, t0); fma2(acc[0][1], wa.x, t1);
            fma2(acc[0][2], wa.x, t2); fma2(acc[0][3], wa.x, t3);
            fma2(acc[1][0], wa.y, t0); fma2(acc[1][1], wa.y, t1);
            fma2(acc[1][2], wa.y, t2); fma2(acc[1][3], wa.y, t3);
            fma2(acc[2][0], wb.x, t0); fma2(acc[2][1], wb.x, t1);
            fma2(acc[2][2], wb.x, t2); fma2(acc[2][3], wb.x, t3);
            fma2(acc[3][0], wb.y, t0); fma2(acc[3][1], wb.y, t1);
            fma2(acc[3][2], wb.y, t2); fma2(acc[3][3], wb.y, t3);
        }

        size_t base = (size_t)(g * 256 + sub * 128 + ocb) * HWd
                    + (bi * 16 + ph * 8) * Wd + bj * 16;
        const float* xp = x + base;
        float*       op = out + base;
#pragma unroll
        for (int p = 0; p < 4; ++p)
#pragma unroll
            for (int k = 0; k < 4; ++k) {
                int px = lane + 32 * k;
                float a, b; upk2(acc[p][k], a, b);
                size_t o = (size_t)(2 * p) * HWd + (px >> 4) * Wd + (px & 15);
                op[o]       = fmaxf(xp[o] + a, 0.f);
                op[o + HWd] = fmaxf(xp[o + HWd] + b, 0.f);
            }
    }
}

// ---------------------------------------------------------------------------
extern "C" void kernel_launch(void* const* d_in, const int* in_sizes, int n_in,
                              void* d_out, int out_size)
{
    (void)in_sizes; (void)n_in; (void)out_size;
    const float* x    = (const float*)d_in[0];
    const float* mask = (const float*)d_in[1];
    const float* w1   = (const float*)d_in[2];
    const float* w2   = (const float*)d_in[3];
    const float* w3   = (const float*)d_in[4];
    float* out = (float*)d_out;

    const int smem1 = (256 * 68 + 16 * 128) * 4;       // 77824
    const int smem2 = (64 * 324 + 144 * 36) * 4;       // 103680
    const int smem3 = (64 * 128 + 64 * 132) * 4;       // 66560
    cudaFuncSetAttribute(k1_conv1, cudaFuncAttributeMaxDynamicSharedMemorySize, smem1);
    cudaFuncSetAttribute(k2_conv2, cudaFuncAttributeMaxDynamicSharedMemorySize, smem2);
    cudaFuncSetAttribute(k3_active, cudaFuncAttributeMaxDynamicSharedMemorySize, smem3);

    k1_conv1<<<513, 256, smem1>>>(x, mask, w1);
    k2_conv2<<<1024, 512, smem2>>>(x, mask, w2, out);
    k3_active<<<1024, 256, smem3>>>(x, w3, out);
}